// round 5
// baseline (speedup 1.0000x reference)
#include <cuda_runtime.h>
#include <math.h>

#define Bsz   4
#define Nseq  2048
#define Dmod  1024
#define NH    16
#define DH    64
#define NLAB  8
#define QKVN  3072
#define NTOK  (Bsz*Nseq)

// Scratch (device globals; no runtime allocation allowed)
__device__ float g_qkv[(size_t)NTOK * QKVN];   // 96 MB: per-token [q|k|v]
__device__ float g_att[(size_t)NTOK * Dmod];   // 32 MB: attention output
__device__ int   g_tok[NTOK];
__device__ int   g_cnt[NLAB];
__device__ int   g_off[NLAB];

// ---------------------------------------------------------------------------
// Stage 0: bucket tokens by label (one block)
// ---------------------------------------------------------------------------
__global__ void bucket_kernel(const int* __restrict__ L) {
    __shared__ int s_cnt[NLAB];
    __shared__ int s_cur[NLAB];
    int t = threadIdx.x;
    if (t < NLAB) s_cnt[t] = 0;
    __syncthreads();
    for (int i = t; i < NTOK; i += blockDim.x) atomicAdd(&s_cnt[L[i]], 1);
    __syncthreads();
    if (t == 0) {
        int acc = 0;
        for (int l = 0; l < NLAB; l++) {
            g_off[l] = acc; s_cur[l] = acc; g_cnt[l] = s_cnt[l]; acc += s_cnt[l];
        }
    }
    __syncthreads();
    for (int i = t; i < NTOK; i += blockDim.x) {
        int l = L[i];
        int p = atomicAdd(&s_cur[l], 1);
        g_tok[p] = i;
    }
}

// ---------------------------------------------------------------------------
// Stage 1: per-label QKV GEMM (gathered rows). 64x64 tile, 4x4 microtile.
// ---------------------------------------------------------------------------
__global__ void qkv_gemm_kernel(const float* __restrict__ X,
                                const float* __restrict__ W,
                                const float* __restrict__ bias) {
    int l   = blockIdx.z;
    int cnt = g_cnt[l];
    int m0  = blockIdx.y * 64;
    if (m0 >= cnt) return;
    int off = g_off[l];
    int n0  = blockIdx.x * 64;

    __shared__ float Xs[16][68];   // [k][m]
    __shared__ float Ws[16][68];   // [k][n]
    __shared__ int   toks[64];

    int tid = threadIdx.x;
    if (tid < 64) {
        int m = m0 + tid;
        toks[tid] = (m < cnt) ? g_tok[off + m] : -1;
    }
    __syncthreads();

    int tx = tid & 15, ty = tid >> 4;
    int lm = tid >> 2;          // 0..63  row for X load
    int lk = (tid & 3) * 4;     // k offset within 16
    int wk = tid >> 4;          // 0..15  k row for W load
    int wn = (tid & 15) * 4;    // n offset

    const float* Wl = W + (size_t)l * Dmod * QKVN;
    int tokm = toks[lm];

    float acc[4][4];
#pragma unroll
    for (int i = 0; i < 4; i++)
#pragma unroll
        for (int j = 0; j < 4; j++) acc[i][j] = 0.f;

    for (int k0 = 0; k0 < Dmod; k0 += 16) {
        float4 xv = make_float4(0.f, 0.f, 0.f, 0.f);
        if (tokm >= 0) xv = *(const float4*)(X + (size_t)tokm * Dmod + k0 + lk);
        Xs[lk + 0][lm] = xv.x; Xs[lk + 1][lm] = xv.y;
        Xs[lk + 2][lm] = xv.z; Xs[lk + 3][lm] = xv.w;

        float4 wv = *(const float4*)(Wl + (size_t)(k0 + wk) * QKVN + n0 + wn);
        *(float4*)&Ws[wk][wn] = wv;
        __syncthreads();

#pragma unroll
        for (int k = 0; k < 16; k++) {
            float4 av = *(const float4*)&Xs[k][ty * 4];
            float4 bv = *(const float4*)&Ws[k][tx * 4];
            float aa[4] = {av.x, av.y, av.z, av.w};
            float bb[4] = {bv.x, bv.y, bv.z, bv.w};
#pragma unroll
            for (int i = 0; i < 4; i++)
#pragma unroll
                for (int j = 0; j < 4; j++) acc[i][j] += aa[i] * bb[j];
        }
        __syncthreads();
    }

    float4 bv = *(const float4*)(bias + (size_t)l * QKVN + n0 + tx * 4);
#pragma unroll
    for (int i = 0; i < 4; i++) {
        int tok = toks[ty * 4 + i];
        if (tok < 0) continue;
        float4 ov;
        ov.x = acc[i][0] + bv.x; ov.y = acc[i][1] + bv.y;
        ov.z = acc[i][2] + bv.z; ov.w = acc[i][3] + bv.w;
        *(float4*)(g_qkv + (size_t)tok * QKVN + n0 + tx * 4) = ov;
    }
}

// ---------------------------------------------------------------------------
// Stage 2: flash-style attention. One block per (q-tile 64, head, batch).
// 256 threads = 16x16, each owns 4x4 of S and 4x4 of O.
// ---------------------------------------------------------------------------
#define ATT_SMEM (4 * 64 * 68 * sizeof(float))

__global__ void attn_kernel() {
    extern __shared__ float sm[];
    float* Qs = sm;                // [d][m], stride 68
    float* Ks = sm + 64 * 68;      // [d][n]
    float* Vs = sm + 2 * 64 * 68;  // [k][d]
    float* Ps = sm + 3 * 64 * 68;  // [k][m]

    int qt = blockIdx.x, h = blockIdx.y, b = blockIdx.z;
    int tid = threadIdx.x;
    int tx = tid & 15, ty = tid >> 4;
    int lm = tid >> 2, lk = (tid & 3) * 4;

    const float* base = g_qkv + (size_t)b * Nseq * QKVN;

    { // load full 64x64 Q tile transposed, pre-scaled by 1/sqrt(DH)
        int q = qt * 64 + lm;
        const float* qrow = base + (size_t)q * QKVN + h * DH;
        const float s = 0.125f;
#pragma unroll
        for (int c = 0; c < 4; c++) {
            int d = c * 16 + lk;
            float4 v = *(const float4*)(qrow + d);
            Qs[(d + 0) * 68 + lm] = v.x * s; Qs[(d + 1) * 68 + lm] = v.y * s;
            Qs[(d + 2) * 68 + lm] = v.z * s; Qs[(d + 3) * 68 + lm] = v.w * s;
        }
    }

    float o[4][4];
    float rm[4], rs[4];
#pragma unroll
    for (int i = 0; i < 4; i++) {
        rm[i] = -1e30f; rs[i] = 0.f;
#pragma unroll
        for (int j = 0; j < 4; j++) o[i][j] = 0.f;
    }

    for (int kt = 0; kt < Nseq / 64; kt++) {
        __syncthreads();  // protect Ks/Vs/Ps vs previous iteration's reads
        { // load full 64x64 K (transposed) and V (natural) tiles
            int kq = kt * 64 + lm;
            const float* krow = base + (size_t)kq * QKVN + Dmod + h * DH;
            const float* vrow = base + (size_t)kq * QKVN + 2 * Dmod + h * DH;
#pragma unroll
            for (int c = 0; c < 4; c++) {
                int d = c * 16 + lk;
                float4 v = *(const float4*)(krow + d);
                Ks[(d + 0) * 68 + lm] = v.x; Ks[(d + 1) * 68 + lm] = v.y;
                Ks[(d + 2) * 68 + lm] = v.z; Ks[(d + 3) * 68 + lm] = v.w;
                float4 w = *(const float4*)(vrow + d);
                *(float4*)&Vs[lm * 68 + d] = w;
            }
        }
        __syncthreads();

        // S = Q K^T (64x64), thread 4x4
        float s4[4][4];
#pragma unroll
        for (int i = 0; i < 4; i++)
#pragma unroll
            for (int j = 0; j < 4; j++) s4[i][j] = 0.f;
#pragma unroll
        for (int d = 0; d < 64; d++) {
            float4 av = *(const float4*)&Qs[d * 68 + ty * 4];
            float4 bv = *(const float4*)&Ks[d * 68 + tx * 4];
            float aa[4] = {av.x, av.y, av.z, av.w};
            float bb[4] = {bv.x, bv.y, bv.z, bv.w};
#pragma unroll
            for (int i = 0; i < 4; i++)
#pragma unroll
                for (int j = 0; j < 4; j++) s4[i][j] += aa[i] * bb[j];
        }

        // online softmax update per row; row group = 16 lanes sharing ty
#pragma unroll
        for (int i = 0; i < 4; i++) {
            float tm = fmaxf(fmaxf(s4[i][0], s4[i][1]), fmaxf(s4[i][2], s4[i][3]));
#pragma unroll
            for (int offv = 8; offv > 0; offv >>= 1)
                tm = fmaxf(tm, __shfl_xor_sync(0xffffffffu, tm, offv));
            float nm = fmaxf(rm[i], tm);
            float c  = __expf(rm[i] - nm);
            float ps = 0.f;
#pragma unroll
            for (int j = 0; j < 4; j++) {
                float p = __expf(s4[i][j] - nm);
                s4[i][j] = p; ps += p;
            }
#pragma unroll
            for (int offv = 8; offv > 0; offv >>= 1)
                ps += __shfl_xor_sync(0xffffffffu, ps, offv);
            rs[i] = rs[i] * c + ps;
            rm[i] = nm;
#pragma unroll
            for (int j = 0; j < 4; j++) {
                o[i][j] *= c;
                Ps[(tx * 4 + j) * 68 + ty * 4 + i] = s4[i][j];  // transposed
            }
        }
        __syncthreads();

        // O += P V (inner over 64 keys)
#pragma unroll
        for (int k = 0; k < 64; k++) {
            float4 av = *(const float4*)&Ps[k * 68 + ty * 4];
            float4 bv = *(const float4*)&Vs[k * 68 + tx * 4];
            float aa[4] = {av.x, av.y, av.z, av.w};
            float bb[4] = {bv.x, bv.y, bv.z, bv.w};
#pragma unroll
            for (int i = 0; i < 4; i++)
#pragma unroll
                for (int j = 0; j < 4; j++) o[i][j] += aa[i] * bb[j];
        }
    }

#pragma unroll
    for (int i = 0; i < 4; i++) {
        float inv = 1.f / rs[i];
        int q = qt * 64 + ty * 4 + i;
        float4 ov;
        ov.x = o[i][0] * inv; ov.y = o[i][1] * inv;
        ov.z = o[i][2] * inv; ov.w = o[i][3] * inv;
        *(float4*)(g_att + ((size_t)b * Nseq + q) * Dmod + h * DH + tx * 4) = ov;
    }
}

// ---------------------------------------------------------------------------
// Stage 3: output projection [8192,1024]@[1024,1024] + bias
// ---------------------------------------------------------------------------
__global__ void proj_kernel(const float* __restrict__ Wp,
                            const float* __restrict__ bp,
                            float* __restrict__ out) {
    int m0 = blockIdx.y * 64;
    int n0 = blockIdx.x * 64;

    __shared__ float Xs[16][68];
    __shared__ float Ws[16][68];

    int tid = threadIdx.x;
    int tx = tid & 15, ty = tid >> 4;
    int lm = tid >> 2;
    int lk = (tid & 3) * 4;
    int wk = tid >> 4;
    int wn = (tid & 15) * 4;

    float acc[4][4];
#pragma unroll
    for (int i = 0; i < 4; i++)
#pragma unroll
        for (int j = 0; j < 4; j++) acc[i][j] = 0.f;

    for (int k0 = 0; k0 < Dmod; k0 += 16) {
        float4 xv = *(const float4*)(g_att + (size_t)(m0 + lm) * Dmod + k0 + lk);
        Xs[lk + 0][lm] = xv.x; Xs[lk + 1][lm] = xv.y;
        Xs[lk + 2][lm] = xv.z; Xs[lk + 3][lm] = xv.w;
        float4 wv = *(const float4*)(Wp + (size_t)(k0 + wk) * Dmod + n0 + wn);
        *(float4*)&Ws[wk][wn] = wv;
        __syncthreads();
#pragma unroll
        for (int k = 0; k < 16; k++) {
            float4 av = *(const float4*)&Xs[k][ty * 4];
            float4 bv = *(const float4*)&Ws[k][tx * 4];
            float aa[4] = {av.x, av.y, av.z, av.w};
            float bb[4] = {bv.x, bv.y, bv.z, bv.w};
#pragma unroll
            for (int i = 0; i < 4; i++)
#pragma unroll
                for (int j = 0; j < 4; j++) acc[i][j] += aa[i] * bb[j];
        }
        __syncthreads();
    }

    float4 bv = *(const float4*)(bp + n0 + tx * 4);
#pragma unroll
    for (int i = 0; i < 4; i++) {
        int m = m0 + ty * 4 + i;
        float4 ov;
        ov.x = acc[i][0] + bv.x; ov.y = acc[i][1] + bv.y;
        ov.z = acc[i][2] + bv.z; ov.w = acc[i][3] + bv.w;
        *(float4*)(out + (size_t)m * Dmod + n0 + tx * 4) = ov;
    }
}

// ---------------------------------------------------------------------------
extern "C" void kernel_launch(void* const* d_in, const int* in_sizes, int n_in,
                              void* d_out, int out_size) {
    const float* X     = (const float*)d_in[0];
    const int*   L     = (const int*)d_in[1];
    const float* Wqkv  = (const float*)d_in[2];
    const float* bqkv  = (const float*)d_in[3];
    const float* Wproj = (const float*)d_in[4];
    const float* bproj = (const float*)d_in[5];
    float* out = (float*)d_out;

    bucket_kernel<<<1, 256>>>(L);
    qkv_gemm_kernel<<<dim3(QKVN / 64, NTOK / 64, NLAB), 256>>>(X, Wqkv, bqkv);
    cudaFuncSetAttribute(attn_kernel, cudaFuncAttributeMaxDynamicSharedMemorySize,
                         (int)ATT_SMEM);
    attn_kernel<<<dim3(Nseq / 64, NH, Bsz), 256, ATT_SMEM>>>();
    proj_kernel<<<dim3(Dmod / 64, NTOK / 64), 256>>>(Wproj, bproj, out);
}